// round 6
// baseline (speedup 1.0000x reference)
#include <cuda_runtime.h>

// LightGCN: K=3 propagation over bipartite graph, symmetric GCN norm (no self loops).
// out = (x + x1 + x2 + x3) / 4, where x_{k+1}[dst] = sum_edges norm(e) * x_k[src].

constexpr int NUM_USERS = 100000;
constexpr int NUM_ITEMS = 50000;
constexpr int EMB       = 64;
constexpr int NE        = 1250000;
constexpr int NN        = NUM_USERS + NUM_ITEMS;
constexpr int NV4       = NN * EMB / 4;           // 2,400,000 float4 elements
constexpr int UV4       = NUM_USERS * EMB / 4;

// Allocation-free scratch (static device globals).
__device__ float g_buf0[(size_t)NN * EMB];
__device__ float g_buf1[(size_t)NN * EMB];
__device__ int   g_deg[NN];
__device__ float g_dis[NN];
__device__ int   g_src[NE];
__device__ int   g_dst[NE];
__device__ float g_norm[NE];
__device__ int   g_is64;

__global__ void k_zero_deg() {
    int i = blockIdx.x * blockDim.x + threadIdx.x;
    if (i < NN) g_deg[i] = 0;
}

// Detect whether edge_index arrived as int64 (little-endian: every odd 32-bit
// word is a zero high-half, since indices are in [0, 150000)) or as int32
// (odd words are random nonzero indices — 64 consecutive zeros is impossible).
__global__ void k_detect(const int* __restrict__ raw) {
    if (threadIdx.x == 0 && blockIdx.x == 0) {
        int is64 = 1;
        #pragma unroll 1
        for (int k = 1; k < 128; k += 2)
            if (raw[k] != 0) { is64 = 0; break; }
        g_is64 = is64;
    }
}

// Extract src/dst as int32 under either layout; count in-degree of dst.
__global__ void k_convert(const int* __restrict__ raw) {
    int e = blockIdx.x * blockDim.x + threadIdx.x;
    if (e >= NE) return;
    int src, dst;
    if (g_is64) {
        src = raw[2 * (size_t)e];
        dst = raw[2 * ((size_t)NE + e)];
    } else {
        src = raw[e];
        dst = raw[NE + e];
    }
    g_src[e] = src;
    g_dst[e] = dst;
    atomicAdd(&g_deg[dst], 1);
}

__global__ void k_dis() {
    int i = blockIdx.x * blockDim.x + threadIdx.x;
    if (i < NN) {
        int d = g_deg[i];
        g_dis[i] = (d > 0) ? rsqrtf((float)d) : 0.0f;
    }
}

__global__ void k_norm() {
    int e = blockIdx.x * blockDim.x + threadIdx.x;
    if (e < NE) g_norm[e] = g_dis[g_src[e]] * g_dis[g_dst[e]];
}

// out = x0 = concat(user, item); buf0 = x0; buf1 = 0.
__global__ void k_init(const float4* __restrict__ uw, const float4* __restrict__ iw,
                       float4* __restrict__ out) {
    int i = blockIdx.x * blockDim.x + threadIdx.x;
    if (i >= NV4) return;
    float4 v = (i < UV4) ? uw[i] : iw[i - UV4];
    reinterpret_cast<float4*>(g_buf0)[i] = v;
    reinterpret_cast<float4*>(g_buf1)[i] = make_float4(0.f, 0.f, 0.f, 0.f);
    out[i] = v;
}

// Push-scatter: 16 threads per edge, one float4 each. DIR=0: buf0 -> buf1; DIR=1: buf1 -> buf0.
template <int DIR>
__global__ void __launch_bounds__(256) k_scatter() {
    const float* __restrict__ xin  = DIR ? g_buf1 : g_buf0;
    float*       __restrict__ xout = DIR ? g_buf0 : g_buf1;

    int t = blockIdx.x * blockDim.x + threadIdx.x;
    int e = t >> 4;
    if (e >= NE) return;
    int sub = t & 15;

    int   src  = __ldg(g_src + e);     // 16 lanes same address -> broadcast
    int   dst  = __ldg(g_dst + e);
    float norm = __ldg(g_norm + e);

    float4 v = reinterpret_cast<const float4*>(xin)[src * 16 + sub];  // coalesced 256B gather

    float* p = xout + (size_t)dst * EMB + sub * 4;
    atomicAdd(p + 0, v.x * norm);
    atomicAdd(p + 1, v.y * norm);
    atomicAdd(p + 2, v.z * norm);
    atomicAdd(p + 3, v.w * norm);
}

// After scatter wrote buf<W>: out += buf<W>; zero buf<1-W> (next step's target).
// FINAL fuses the /(K+1) scale and skips the zero.
template <int W, bool FINAL>
__global__ void k_acc(float4* __restrict__ out) {
    int i = blockIdx.x * blockDim.x + threadIdx.x;
    if (i >= NV4) return;
    const float4* __restrict__ xnew = reinterpret_cast<const float4*>(W ? g_buf1 : g_buf0);
    float4*       __restrict__ zb   = reinterpret_cast<float4*>(W ? g_buf0 : g_buf1);

    float4 x = xnew[i];
    float4 o = out[i];
    o.x += x.x; o.y += x.y; o.z += x.z; o.w += x.w;
    if (FINAL) {
        o.x *= 0.25f; o.y *= 0.25f; o.z *= 0.25f; o.w *= 0.25f;
    } else {
        zb[i] = make_float4(0.f, 0.f, 0.f, 0.f);
    }
    out[i] = o;
}

extern "C" void kernel_launch(void* const* d_in, const int* in_sizes, int n_in,
                              void* d_out, int out_size) {
    const float4* uw  = (const float4*)d_in[0];
    const float4* iw  = (const float4*)d_in[1];
    const int*    ei  = (const int*)d_in[2];
    float4*       out = (float4*)d_out;

    const int B = 256;
    const int G_NN  = (NN  + B - 1) / B;
    const int G_NE  = (NE  + B - 1) / B;
    const int G_NV4 = (NV4 + B - 1) / B;
    const int G_SC  = (NE * 16 + B - 1) / B;

    k_zero_deg<<<G_NN, B>>>();
    k_detect<<<1, 32>>>(ei);
    k_convert<<<G_NE, B>>>(ei);
    k_dis<<<G_NN, B>>>();
    k_norm<<<G_NE, B>>>();
    k_init<<<G_NV4, B>>>(uw, iw, out);

    // Step 1: buf0 -> buf1
    k_scatter<0><<<G_SC, B>>>();
    k_acc<1, false><<<G_NV4, B>>>(out);   // out += buf1, zero buf0
    // Step 2: buf1 -> buf0
    k_scatter<1><<<G_SC, B>>>();
    k_acc<0, false><<<G_NV4, B>>>(out);   // out += buf0, zero buf1
    // Step 3: buf0 -> buf1
    k_scatter<0><<<G_SC, B>>>();
    k_acc<1, true><<<G_NV4, B>>>(out);    // out = (out + buf1) * 0.25
}

// round 7
// speedup vs baseline: 2.9687x; 2.9687x over previous
#include <cuda_runtime.h>

// LightGCN: K=3 propagation, symmetric GCN norm, pull-based CSR (no float atomics).
// out = (x0 + x1 + x2 + x3) / 4,  x_{k+1}[d] = sum_{(s->d)} norm(e) * x_k[s].

constexpr int NUM_USERS = 100000;
constexpr int NUM_ITEMS = 50000;
constexpr int EMB       = 64;
constexpr int NE        = 1250000;
constexpr int NN        = NUM_USERS + NUM_ITEMS;
constexpr int NV4       = NN * EMB / 4;           // 2,400,000 float4
constexpr int UV4       = NUM_USERS * EMB / 4;
constexpr int NB        = (NN + 255) / 256;       // 586 scan blocks

// Allocation-free scratch (static device globals).
__device__ float  g_buf0[(size_t)NN * EMB];
__device__ float  g_buf1[(size_t)NN * EMB];
__device__ int    g_deg[NN];
__device__ float  g_dis[NN];
__device__ int    g_src[NE];
__device__ int    g_dst[NE];
__device__ int    g_rowoff[NN];    // CSR row start
__device__ int    g_cursor[NN];    // fill cursor (copy of rowoff, bumped)
__device__ float2 g_csr[NE];       // {src (bitcast int), norm}
__device__ int    g_excl[NN];      // per-element exclusive prefix within block
__device__ int    g_bsum[NB];      // per-block totals
__device__ int    g_bpre[NB];      // exclusive prefix of block totals
__device__ int    g_is64;

__global__ void k_zero_deg() {
    int i = blockIdx.x * blockDim.x + threadIdx.x;
    if (i < NN) g_deg[i] = 0;
}

// Detect int64 vs int32 storage of edge_index (indices < 150000 => int64
// little-endian has zero high words at all odd int32 positions).
__global__ void k_detect(const int* __restrict__ raw) {
    if (threadIdx.x == 0 && blockIdx.x == 0) {
        int is64 = 1;
        #pragma unroll 1
        for (int k = 1; k < 128; k += 2)
            if (raw[k] != 0) { is64 = 0; break; }
        g_is64 = is64;
    }
}

// Extract src/dst as int32; count in-degree of dst.
__global__ void k_convert(const int* __restrict__ raw) {
    int e = blockIdx.x * blockDim.x + threadIdx.x;
    if (e >= NE) return;
    int src, dst;
    if (g_is64) {
        src = raw[2 * (size_t)e];
        dst = raw[2 * ((size_t)NE + e)];
    } else {
        src = raw[e];
        dst = raw[NE + e];
    }
    g_src[e] = src;
    g_dst[e] = dst;
    atomicAdd(&g_deg[dst], 1);
}

__global__ void k_dis() {
    int i = blockIdx.x * blockDim.x + threadIdx.x;
    if (i < NN) {
        int d = g_deg[i];
        g_dis[i] = (d > 0) ? rsqrtf((float)d) : 0.0f;
    }
}

// ---- 3-phase exclusive scan of g_deg -> g_rowoff / g_cursor ----
__global__ void k_scan1() {
    __shared__ int s[256];
    int t = threadIdx.x;
    int i = blockIdx.x * 256 + t;
    int v = (i < NN) ? g_deg[i] : 0;
    s[t] = v;
    __syncthreads();
    #pragma unroll
    for (int o = 1; o < 256; o <<= 1) {
        int x = (t >= o) ? s[t - o] : 0;
        __syncthreads();
        s[t] += x;
        __syncthreads();
    }
    if (i < NN) g_excl[i] = s[t] - v;          // exclusive within block
    if (t == 255) g_bsum[blockIdx.x] = s[255]; // block total
}

__global__ void k_scan2() {   // single block of 1024 threads scans NB block sums
    __shared__ int s[1024];
    int t = threadIdx.x;
    int v = (t < NB) ? g_bsum[t] : 0;
    s[t] = v;
    __syncthreads();
    #pragma unroll
    for (int o = 1; o < 1024; o <<= 1) {
        int x = (t >= o) ? s[t - o] : 0;
        __syncthreads();
        s[t] += x;
        __syncthreads();
    }
    if (t < NB) g_bpre[t] = s[t] - v;          // exclusive prefix of blocks
}

__global__ void k_scan3() {
    int i = blockIdx.x * blockDim.x + threadIdx.x;
    if (i >= NN) return;
    int off = g_excl[i] + g_bpre[i >> 8];
    g_rowoff[i] = off;
    g_cursor[i] = off;
}

// Fill CSR: slot per edge via atomic cursor; pack {src, norm} into one float2.
__global__ void k_fill() {
    int e = blockIdx.x * blockDim.x + threadIdx.x;
    if (e >= NE) return;
    int src = g_src[e];
    int dst = g_dst[e];
    float norm = __ldg(g_dis + src) * __ldg(g_dis + dst);
    int pos = atomicAdd(&g_cursor[dst], 1);
    g_csr[pos] = make_float2(__int_as_float(src), norm);
}

// buf0 = x0 = concat(user, item); out = x0.
__global__ void k_init(const float4* __restrict__ uw, const float4* __restrict__ iw,
                       float4* __restrict__ out) {
    int i = blockIdx.x * blockDim.x + threadIdx.x;
    if (i >= NV4) return;
    float4 v = (i < UV4) ? uw[i] : iw[i - UV4];
    reinterpret_cast<float4*>(g_buf0)[i] = v;
    out[i] = v;
}

// Pull: 16 threads per destination row (one float4 lane each). No atomics.
// DIR=0: buf0 -> buf1; DIR=1: buf1 -> buf0. Fuses out-accumulation; FINAL fuses /4.
template <int DIR, bool FINAL>
__global__ void __launch_bounds__(256) k_pull(float4* __restrict__ out) {
    const float4* __restrict__ xin  =
        reinterpret_cast<const float4*>(DIR ? g_buf1 : g_buf0);
    float4* __restrict__ xout =
        reinterpret_cast<float4*>(DIR ? g_buf0 : g_buf1);

    int t = blockIdx.x * blockDim.x + threadIdx.x;
    int n = t >> 4;
    if (n >= NN) return;
    int sub = t & 15;

    int start = __ldg(g_rowoff + n);   // 16 lanes same addr -> broadcast
    int d     = __ldg(g_deg + n);

    float4 acc = make_float4(0.f, 0.f, 0.f, 0.f);
    #pragma unroll 2
    for (int j = start; j < start + d; j++) {
        float2 en  = __ldg(g_csr + j);           // broadcast {src, norm}
        int    src = __float_as_int(en.x);
        float  nm  = en.y;
        float4 v = __ldg(xin + src * 16 + sub);  // coalesced 256B gather
        acc.x += v.x * nm; acc.y += v.y * nm;
        acc.z += v.z * nm; acc.w += v.w * nm;
    }

    int i = n * 16 + sub;
    float4 o = out[i];
    o.x += acc.x; o.y += acc.y; o.z += acc.z; o.w += acc.w;
    if (FINAL) {
        o.x *= 0.25f; o.y *= 0.25f; o.z *= 0.25f; o.w *= 0.25f;
    } else {
        xout[i] = acc;   // full overwrite: no zeroing needed anywhere
    }
    out[i] = o;
}

extern "C" void kernel_launch(void* const* d_in, const int* in_sizes, int n_in,
                              void* d_out, int out_size) {
    const float4* uw  = (const float4*)d_in[0];
    const float4* iw  = (const float4*)d_in[1];
    const int*    ei  = (const int*)d_in[2];
    float4*       out = (float4*)d_out;

    const int B = 256;
    const int G_NN   = (NN  + B - 1) / B;
    const int G_NE   = (NE  + B - 1) / B;
    const int G_NV4  = (NV4 + B - 1) / B;
    const int G_PULL = (NN * 16 + B - 1) / B;

    // Preprocess: degrees, norms, CSR (rebuilt every replay; deterministic).
    k_zero_deg<<<G_NN, B>>>();
    k_detect<<<1, 32>>>(ei);
    k_convert<<<G_NE, B>>>(ei);
    k_dis<<<G_NN, B>>>();
    k_scan1<<<NB, 256>>>();
    k_scan2<<<1, 1024>>>();
    k_scan3<<<G_NN, B>>>();
    k_fill<<<G_NE, B>>>();
    k_init<<<G_NV4, B>>>(uw, iw, out);

    // K=3 propagation, out-accumulation fused into each pull.
    k_pull<0, false><<<G_PULL, B>>>(out);  // buf0 -> buf1, out += x1
    k_pull<1, false><<<G_PULL, B>>>(out);  // buf1 -> buf0, out += x2
    k_pull<0, true ><<<G_PULL, B>>>(out);  // buf0 -> (out + x3) * 0.25
}

// round 8
// speedup vs baseline: 3.5634x; 1.2003x over previous
#include <cuda_runtime.h>

// LightGCN: K=3 propagation, symmetric GCN norm, pull-based CSR (no float atomics).
// out = (x0 + x1 + x2 + x3) / 4,  x_{k+1}[d] = sum_{(s->d)} norm(e) * x_k[s].
// x1 -> bufA, x2 -> bufB, x3 stays in registers; out written exactly once.

constexpr int NUM_USERS = 100000;
constexpr int NUM_ITEMS = 50000;
constexpr int EMB       = 64;
constexpr int NE        = 1250000;
constexpr int NN        = NUM_USERS + NUM_ITEMS;
constexpr int UV4       = NUM_USERS * EMB / 4;
constexpr int NB        = (NN + 255) / 256;       // 586 scan blocks

// Allocation-free scratch (static device globals).
__device__ float  g_bufA[(size_t)NN * EMB];   // x1
__device__ float  g_bufB[(size_t)NN * EMB];   // x2
__device__ int    g_deg[NN];
__device__ float  g_dis[NN];
__device__ int    g_src[NE];
__device__ int    g_dst[NE];
__device__ int    g_rowoff[NN];    // CSR row start
__device__ int    g_cursor[NN];    // fill cursor
__device__ float2 g_csr[NE];       // {src (bitcast int), norm}
__device__ int    g_excl[NN];      // exclusive prefix within block
__device__ int    g_bsum[NB];      // per-block totals
__device__ int    g_is64;

// Zero degrees; block 0 / thread 0 also detects int64-vs-int32 edge storage
// (indices < 150000 => int64 little-endian has zero high words at odd positions).
__global__ void k_pre(const int* __restrict__ raw) {
    int i = blockIdx.x * blockDim.x + threadIdx.x;
    if (i < NN) g_deg[i] = 0;
    if (i == 0) {
        int is64 = 1;
        #pragma unroll 1
        for (int k = 1; k < 128; k += 2)
            if (raw[k] != 0) { is64 = 0; break; }
        g_is64 = is64;
    }
}

// Extract src/dst as int32; count in-degree of dst.
__global__ void k_convert(const int* __restrict__ raw) {
    int e = blockIdx.x * blockDim.x + threadIdx.x;
    if (e >= NE) return;
    int src, dst;
    if (g_is64) {
        src = raw[2 * (size_t)e];
        dst = raw[2 * ((size_t)NE + e)];
    } else {
        src = raw[e];
        dst = raw[NE + e];
    }
    g_src[e] = src;
    g_dst[e] = dst;
    atomicAdd(&g_deg[dst], 1);
}

// Block-local exclusive scan of deg; also computes dis = deg^{-1/2} (0 for isolated).
__global__ void k_scan1() {
    __shared__ int s[256];
    int t = threadIdx.x;
    int i = blockIdx.x * 256 + t;
    int v = 0;
    if (i < NN) {
        v = g_deg[i];
        g_dis[i] = (v > 0) ? rsqrtf((float)v) : 0.0f;
    }
    s[t] = v;
    __syncthreads();
    #pragma unroll
    for (int o = 1; o < 256; o <<= 1) {
        int x = (t >= o) ? s[t - o] : 0;
        __syncthreads();
        s[t] += x;
        __syncthreads();
    }
    if (i < NN) g_excl[i] = s[t] - v;
    if (t == 255) g_bsum[blockIdx.x] = s[255];
}

// Each block reduces its own prefix over g_bsum (NB=586, trivial), then emits
// rowoff/cursor. Replaces the separate middle-scan kernel.
__global__ void k_scan2() {
    __shared__ int sm[256];
    int b = blockIdx.x;
    int t = threadIdx.x;
    int partial = 0;
    for (int k = t; k < b; k += 256) partial += g_bsum[k];
    sm[t] = partial;
    __syncthreads();
    #pragma unroll
    for (int o = 128; o > 0; o >>= 1) {
        if (t < o) sm[t] += sm[t + o];
        __syncthreads();
    }
    int pre = sm[0];
    int i = b * 256 + t;
    if (i < NN) {
        int off = g_excl[i] + pre;
        g_rowoff[i] = off;
        g_cursor[i] = off;
    }
}

// Fill CSR: slot per edge via atomic cursor; pack {src, norm} into one float2.
__global__ void k_fill() {
    int e = blockIdx.x * blockDim.x + threadIdx.x;
    if (e >= NE) return;
    int src = g_src[e];
    int dst = g_dst[e];
    float norm = __ldg(g_dis + src) * __ldg(g_dis + dst);
    int pos = atomicAdd(&g_cursor[dst], 1);
    g_csr[pos] = make_float2(__int_as_float(src), norm);
}

// Pull: 16 threads per destination row (one float4 lane each). No atomics.
// STEP 1: gather x0 from uw/iw -> bufA
// STEP 2: gather bufA -> bufB
// STEP 3: gather bufB -> out = (x0 + bufA + bufB + acc) * 0.25
template <int STEP>
__global__ void __launch_bounds__(256) k_pull(const float4* __restrict__ uw,
                                              const float4* __restrict__ iw,
                                              float4* __restrict__ out) {
    int t = blockIdx.x * blockDim.x + threadIdx.x;
    int n = t >> 4;
    if (n >= NN) return;
    int sub = t & 15;

    int start = __ldg(g_rowoff + n);   // 16 lanes same addr -> broadcast
    int d     = __ldg(g_deg + n);

    const float4* __restrict__ bufA = reinterpret_cast<const float4*>(g_bufA);
    const float4* __restrict__ bufB = reinterpret_cast<const float4*>(g_bufB);

    float4 acc = make_float4(0.f, 0.f, 0.f, 0.f);
    #pragma unroll 4
    for (int j = start; j < start + d; j++) {
        float2 en  = __ldg(g_csr + j);           // broadcast {src, norm}
        int    src = __float_as_int(en.x);
        float  nm  = en.y;
        float4 v;
        if (STEP == 1) {
            v = (src < NUM_USERS) ? __ldg(uw + src * 16 + sub)
                                  : __ldg(iw + (src - NUM_USERS) * 16 + sub);
        } else if (STEP == 2) {
            v = __ldg(bufA + src * 16 + sub);
        } else {
            v = __ldg(bufB + src * 16 + sub);
        }
        acc.x += v.x * nm; acc.y += v.y * nm;
        acc.z += v.z * nm; acc.w += v.w * nm;
    }

    int i = n * 16 + sub;
    if (STEP == 1) {
        reinterpret_cast<float4*>(g_bufA)[i] = acc;
    } else if (STEP == 2) {
        reinterpret_cast<float4*>(g_bufB)[i] = acc;
    } else {
        float4 x0 = (i < UV4) ? __ldg(uw + i) : __ldg(iw + (i - UV4));
        float4 x1 = bufA[i];
        float4 x2 = bufB[i];
        float4 o;
        o.x = (x0.x + x1.x + x2.x + acc.x) * 0.25f;
        o.y = (x0.y + x1.y + x2.y + acc.y) * 0.25f;
        o.z = (x0.z + x1.z + x2.z + acc.z) * 0.25f;
        o.w = (x0.w + x1.w + x2.w + acc.w) * 0.25f;
        out[i] = o;
    }
}

extern "C" void kernel_launch(void* const* d_in, const int* in_sizes, int n_in,
                              void* d_out, int out_size) {
    const float4* uw  = (const float4*)d_in[0];
    const float4* iw  = (const float4*)d_in[1];
    const int*    ei  = (const int*)d_in[2];
    float4*       out = (float4*)d_out;

    const int B = 256;
    const int G_NE   = (NE + B - 1) / B;
    const int G_PULL = (NN * 16 + B - 1) / B;

    // Preprocess: degrees+detect, extract+count, scan(+dis), offsets, CSR fill.
    k_pre<<<NB, B>>>(ei);
    k_convert<<<G_NE, B>>>(ei);
    k_scan1<<<NB, B>>>();
    k_scan2<<<NB, B>>>();
    k_fill<<<G_NE, B>>>();

    // K=3 propagation; out written once by the final step.
    k_pull<1><<<G_PULL, B>>>(uw, iw, out);
    k_pull<2><<<G_PULL, B>>>(uw, iw, out);
    k_pull<3><<<G_PULL, B>>>(uw, iw, out);
}

// round 10
// speedup vs baseline: 3.9056x; 1.0961x over previous
#include <cuda_runtime.h>

// LightGCN: K=3 propagation, symmetric GCN norm, pull-based CSR (no float atomics).
// out = (x0 + x1 + x2 + x3) / 4,  x_{k+1}[d] = sum_{(s->d)} norm(e) * x_k[s].
// x1 -> bufA, x2 -> bufB, x3 stays in registers; out written exactly once (streaming).

constexpr int NUM_USERS = 100000;
constexpr int NUM_ITEMS = 50000;
constexpr int EMB       = 64;
constexpr int NE        = 1250000;
constexpr int NN        = NUM_USERS + NUM_ITEMS;
constexpr int UV4       = NUM_USERS * EMB / 4;
constexpr int NB        = (NN + 255) / 256;       // 586 scan blocks

// Allocation-free scratch (static device globals).
__device__ float  g_bufA[(size_t)NN * EMB];   // x1
__device__ float  g_bufB[(size_t)NN * EMB];   // x2
__device__ int    g_deg[NN];
__device__ float  g_dis[NN];
__device__ int    g_rowoff[NN];    // CSR row start
__device__ int    g_cursor[NN];    // fill cursor
__device__ float2 g_csr[NE];       // {src (bitcast int), norm}
__device__ int    g_excl[NN];      // exclusive prefix within block
__device__ int    g_bsum[NB];      // per-block totals
__device__ int    g_is64;

// Zero degrees; thread 0 also detects int64-vs-int32 edge storage
// (indices < 150000 => int64 little-endian has zero high words at odd positions).
__global__ void k_pre(const int* __restrict__ raw) {
    int i = blockIdx.x * blockDim.x + threadIdx.x;
    if (i < NN) g_deg[i] = 0;
    if (i == 0) {
        int is64 = 1;
        #pragma unroll 1
        for (int k = 1; k < 128; k += 2)
            if (raw[k] != 0) { is64 = 0; break; }
        g_is64 = is64;
    }
}

// Count in-degree of dst straight from the raw edge buffer (no staging arrays).
__global__ void k_count(const int* __restrict__ raw) {
    int e = blockIdx.x * blockDim.x + threadIdx.x;
    if (e >= NE) return;
    int dst = g_is64 ? raw[2 * ((size_t)NE + e)] : raw[NE + e];
    atomicAdd(&g_deg[dst], 1);
}

// Block-local exclusive scan of deg; also computes dis = deg^{-1/2} (0 for isolated).
__global__ void k_scan1() {
    __shared__ int s[256];
    int t = threadIdx.x;
    int i = blockIdx.x * 256 + t;
    int v = 0;
    if (i < NN) {
        v = g_deg[i];
        g_dis[i] = (v > 0) ? rsqrtf((float)v) : 0.0f;
    }
    s[t] = v;
    __syncthreads();
    #pragma unroll
    for (int o = 1; o < 256; o <<= 1) {
        int x = (t >= o) ? s[t - o] : 0;
        __syncthreads();
        s[t] += x;
        __syncthreads();
    }
    if (i < NN) g_excl[i] = s[t] - v;
    if (t == 255) g_bsum[blockIdx.x] = s[255];
}

// Each block reduces its own prefix over g_bsum (NB=586), emits rowoff/cursor.
__global__ void k_scan2() {
    __shared__ int sm[256];
    int b = blockIdx.x;
    int t = threadIdx.x;
    int partial = 0;
    for (int k = t; k < b; k += 256) partial += g_bsum[k];
    sm[t] = partial;
    __syncthreads();
    #pragma unroll
    for (int o = 128; o > 0; o >>= 1) {
        if (t < o) sm[t] += sm[t + o];
        __syncthreads();
    }
    int pre = sm[0];
    int i = b * 256 + t;
    if (i < NN) {
        int off = g_excl[i] + pre;
        g_rowoff[i] = off;
        g_cursor[i] = off;
    }
}

// Fill CSR: slot per edge via atomic cursor; pack {src, norm} into one float2.
// Re-reads the raw edge buffer (L2-hot after k_count).
__global__ void k_fill(const int* __restrict__ raw) {
    int e = blockIdx.x * blockDim.x + threadIdx.x;
    if (e >= NE) return;
    int src, dst;
    if (g_is64) {
        src = raw[2 * (size_t)e];
        dst = raw[2 * ((size_t)NE + e)];
    } else {
        src = raw[e];
        dst = raw[NE + e];
    }
    float norm = __ldg(g_dis + src) * __ldg(g_dis + dst);
    int pos = atomicAdd(&g_cursor[dst], 1);
    g_csr[pos] = make_float2(__int_as_float(src), norm);
}

// Pull: 16 threads per destination row (one float4 lane each). No atomics.
// Inner loop processes edge PAIRS (unroll 2) => 4 independent gathers in flight.
// STEP 1: gather x0 from uw/iw -> bufA
// STEP 2: gather bufA -> bufB
// STEP 3: gather bufB -> out = (x0 + bufA + bufB + acc) * 0.25   (streaming store)
template <int STEP>
__global__ void __launch_bounds__(256) k_pull(const float4* __restrict__ uw,
                                              const float4* __restrict__ iw,
                                              float4* __restrict__ out) {
    int t = blockIdx.x * blockDim.x + threadIdx.x;
    int n = t >> 4;
    if (n >= NN) return;
    int sub = t & 15;

    int start = __ldg(g_rowoff + n);   // 16 lanes same addr -> broadcast
    int d     = __ldg(g_deg + n);
    int end   = start + d;

    const float4* __restrict__ bufA = reinterpret_cast<const float4*>(g_bufA);
    const float4* __restrict__ bufB = reinterpret_cast<const float4*>(g_bufB);

    auto gather = [&](int src) -> float4 {
        if (STEP == 1) {
            return (src < NUM_USERS) ? __ldg(uw + src * 16 + sub)
                                     : __ldg(iw + (src - NUM_USERS) * 16 + sub);
        } else if (STEP == 2) {
            return __ldg(bufA + src * 16 + sub);
        } else {
            return __ldg(bufB + src * 16 + sub);
        }
    };

    float4 acc = make_float4(0.f, 0.f, 0.f, 0.f);
    int j = start;
    #pragma unroll 2
    for (; j + 2 <= end; j += 2) {
        float2 e0 = __ldg(g_csr + j);
        float2 e1 = __ldg(g_csr + j + 1);
        float4 v0 = gather(__float_as_int(e0.x));
        float4 v1 = gather(__float_as_int(e1.x));
        acc.x += v0.x * e0.y; acc.y += v0.y * e0.y;
        acc.z += v0.z * e0.y; acc.w += v0.w * e0.y;
        acc.x += v1.x * e1.y; acc.y += v1.y * e1.y;
        acc.z += v1.z * e1.y; acc.w += v1.w * e1.y;
    }
    if (j < end) {
        float2 e0 = __ldg(g_csr + j);
        float4 v0 = gather(__float_as_int(e0.x));
        acc.x += v0.x * e0.y; acc.y += v0.y * e0.y;
        acc.z += v0.z * e0.y; acc.w += v0.w * e0.y;
    }

    int i = n * 16 + sub;
    if (STEP == 1) {
        reinterpret_cast<float4*>(g_bufA)[i] = acc;
    } else if (STEP == 2) {
        reinterpret_cast<float4*>(g_bufB)[i] = acc;
    } else {
        float4 x0 = (i < UV4) ? __ldg(uw + i) : __ldg(iw + (i - UV4));
        float4 x1 = bufA[i];
        float4 x2 = bufB[i];
        float4 o;
        o.x = (x0.x + x1.x + x2.x + acc.x) * 0.25f;
        o.y = (x0.y + x1.y + x2.y + acc.y) * 0.25f;
        o.z = (x0.z + x1.z + x2.z + acc.z) * 0.25f;
        o.w = (x0.w + x1.w + x2.w + acc.w) * 0.25f;
        __stcs(out + i, o);   // evict-first: out is never re-read, keep L2 for gathers
    }
}

extern "C" void kernel_launch(void* const* d_in, const int* in_sizes, int n_in,
                              void* d_out, int out_size) {
    const float4* uw  = (const float4*)d_in[0];
    const float4* iw  = (const float4*)d_in[1];
    const int*    ei  = (const int*)d_in[2];
    float4*       out = (float4*)d_out;

    const int B = 256;
    const int G_NE   = (NE + B - 1) / B;
    const int G_PULL = (NN * 16 + B - 1) / B;

    // Preprocess: degrees+detect, count, scan(+dis), offsets, CSR fill.
    k_pre<<<NB, B>>>(ei);
    k_count<<<G_NE, B>>>(ei);
    k_scan1<<<NB, B>>>();
    k_scan2<<<NB, B>>>();
    k_fill<<<G_NE, B>>>(ei);

    // K=3 propagation; out written once by the final step.
    k_pull<1><<<G_PULL, B>>>(uw, iw, out);
    k_pull<2><<<G_PULL, B>>>(uw, iw, out);
    k_pull<3><<<G_PULL, B>>>(uw, iw, out);
}

// round 11
// speedup vs baseline: 4.6357x; 1.1869x over previous
#include <cuda_runtime.h>
#include <cuda_fp16.h>

// LightGCN: K=3 propagation, symmetric GCN norm, pull-based CSR (no float atomics).
// out = (x0 + x1 + x2 + x3) / 4,  x_{k+1}[d] = sum_{(s->d)} norm(e) * x_k[s].
// x1 -> bufA (fp16), x2 -> bufB (fp16), x3 stays in fp32 registers.
// All accumulation in fp32; fp16 only at storage (rel_err budget 1e-3, cost ~1e-4).

constexpr int NUM_USERS = 100000;
constexpr int NUM_ITEMS = 50000;
constexpr int EMB       = 64;
constexpr int NE        = 1250000;
constexpr int NN        = NUM_USERS + NUM_ITEMS;
constexpr int NB        = (NN + 255) / 256;       // 586 scan blocks

// Allocation-free scratch. Half buffers as uint4 for 16B alignment:
// one node row = 64 halves = 128 B = 8 uint4.
__device__ uint4  g_bufA[(size_t)NN * 8];   // x1 (fp16)
__device__ uint4  g_bufB[(size_t)NN * 8];   // x2 (fp16)
__device__ int    g_deg[NN];
__device__ float  g_dis[NN];
__device__ int    g_rowoff[NN];
__device__ int    g_cursor[NN];
__device__ float2 g_csr[NE];       // {src (bitcast int), norm}
__device__ int    g_excl[NN];
__device__ int    g_bsum[NB];
__device__ int    g_is64;

// Zero degrees; thread 0 detects int64-vs-int32 edge storage.
__global__ void k_pre(const int* __restrict__ raw) {
    int i = blockIdx.x * blockDim.x + threadIdx.x;
    if (i < NN) g_deg[i] = 0;
    if (i == 0) {
        int is64 = 1;
        #pragma unroll 1
        for (int k = 1; k < 128; k += 2)
            if (raw[k] != 0) { is64 = 0; break; }
        g_is64 = is64;
    }
}

__global__ void k_count(const int* __restrict__ raw) {
    int e = blockIdx.x * blockDim.x + threadIdx.x;
    if (e >= NE) return;
    int dst = g_is64 ? raw[2 * ((size_t)NE + e)] : raw[NE + e];
    atomicAdd(&g_deg[dst], 1);
}

// Block-local exclusive scan of deg; also dis = deg^{-1/2} (0 for isolated).
__global__ void k_scan1() {
    __shared__ int s[256];
    int t = threadIdx.x;
    int i = blockIdx.x * 256 + t;
    int v = 0;
    if (i < NN) {
        v = g_deg[i];
        g_dis[i] = (v > 0) ? rsqrtf((float)v) : 0.0f;
    }
    s[t] = v;
    __syncthreads();
    #pragma unroll
    for (int o = 1; o < 256; o <<= 1) {
        int x = (t >= o) ? s[t - o] : 0;
        __syncthreads();
        s[t] += x;
        __syncthreads();
    }
    if (i < NN) g_excl[i] = s[t] - v;
    if (t == 255) g_bsum[blockIdx.x] = s[255];
}

// Each block reduces its own prefix over g_bsum, emits rowoff/cursor.
__global__ void k_scan2() {
    __shared__ int sm[256];
    int b = blockIdx.x;
    int t = threadIdx.x;
    int partial = 0;
    for (int k = t; k < b; k += 256) partial += g_bsum[k];
    sm[t] = partial;
    __syncthreads();
    #pragma unroll
    for (int o = 128; o > 0; o >>= 1) {
        if (t < o) sm[t] += sm[t + o];
        __syncthreads();
    }
    int pre = sm[0];
    int i = b * 256 + t;
    if (i < NN) {
        int off = g_excl[i] + pre;
        g_rowoff[i] = off;
        g_cursor[i] = off;
    }
}

// Fill CSR: slot per edge via atomic cursor; pack {src, norm} into one float2.
__global__ void k_fill(const int* __restrict__ raw) {
    int e = blockIdx.x * blockDim.x + threadIdx.x;
    if (e >= NE) return;
    int src, dst;
    if (g_is64) {
        src = raw[2 * (size_t)e];
        dst = raw[2 * ((size_t)NE + e)];
    } else {
        src = raw[e];
        dst = raw[NE + e];
    }
    float norm = __ldg(g_dis + src) * __ldg(g_dis + dst);
    int pos = atomicAdd(&g_cursor[dst], 1);
    g_csr[pos] = make_float2(__int_as_float(src), norm);
}

// STEP 1: 16 lanes/row. Gather x0 (fp32) from uw/iw, write bufA as fp16.
__global__ void __launch_bounds__(256) k_pull1(const float4* __restrict__ uw,
                                               const float4* __restrict__ iw) {
    int t = blockIdx.x * blockDim.x + threadIdx.x;
    int n = t >> 4;
    if (n >= NN) return;
    int sub = t & 15;

    int start = __ldg(g_rowoff + n);
    int d     = __ldg(g_deg + n);
    int end   = start + d;

    float4 acc = make_float4(0.f, 0.f, 0.f, 0.f);
    int j = start;
    #pragma unroll 2
    for (; j + 2 <= end; j += 2) {
        float2 e0 = __ldg(g_csr + j);
        float2 e1 = __ldg(g_csr + j + 1);
        int s0 = __float_as_int(e0.x), s1 = __float_as_int(e1.x);
        float4 v0 = (s0 < NUM_USERS) ? __ldg(uw + s0 * 16 + sub)
                                     : __ldg(iw + (s0 - NUM_USERS) * 16 + sub);
        float4 v1 = (s1 < NUM_USERS) ? __ldg(uw + s1 * 16 + sub)
                                     : __ldg(iw + (s1 - NUM_USERS) * 16 + sub);
        acc.x += v0.x * e0.y; acc.y += v0.y * e0.y;
        acc.z += v0.z * e0.y; acc.w += v0.w * e0.y;
        acc.x += v1.x * e1.y; acc.y += v1.y * e1.y;
        acc.z += v1.z * e1.y; acc.w += v1.w * e1.y;
    }
    if (j < end) {
        float2 e0 = __ldg(g_csr + j);
        int s0 = __float_as_int(e0.x);
        float4 v0 = (s0 < NUM_USERS) ? __ldg(uw + s0 * 16 + sub)
                                     : __ldg(iw + (s0 - NUM_USERS) * 16 + sub);
        acc.x += v0.x * e0.y; acc.y += v0.y * e0.y;
        acc.z += v0.z * e0.y; acc.w += v0.w * e0.y;
    }

    // 4 floats -> 2 half2 -> 8B store. 16 lanes x 8B = 128B coalesced row.
    __half2 h0 = __floats2half2_rn(acc.x, acc.y);
    __half2 h1 = __floats2half2_rn(acc.z, acc.w);
    uint2 w;
    w.x = *reinterpret_cast<unsigned*>(&h0);
    w.y = *reinterpret_cast<unsigned*>(&h1);
    reinterpret_cast<uint2*>(g_bufA)[n * 16 + sub] = w;
}

// STEPS 2/3: 8 lanes/row, each lane owns 8 halves (one uint4 = 16B).
// Gather fp16, accumulate fp32. STEP2: bufA -> bufB.
// STEP3: bufB -> out = (x0 + x1 + x2 + acc) * 0.25, streaming store.
__device__ __forceinline__ void acc8(float* a, uint4 r, float nm) {
    __half2 h;
    float2 f;
    *reinterpret_cast<unsigned*>(&h) = r.x; f = __half22float2(h);
    a[0] += f.x * nm; a[1] += f.y * nm;
    *reinterpret_cast<unsigned*>(&h) = r.y; f = __half22float2(h);
    a[2] += f.x * nm; a[3] += f.y * nm;
    *reinterpret_cast<unsigned*>(&h) = r.z; f = __half22float2(h);
    a[4] += f.x * nm; a[5] += f.y * nm;
    *reinterpret_cast<unsigned*>(&h) = r.w; f = __half22float2(h);
    a[6] += f.x * nm; a[7] += f.y * nm;
}

template <int STEP>
__global__ void __launch_bounds__(256) k_pull_h(const float4* __restrict__ uw,
                                                const float4* __restrict__ iw,
                                                float4* __restrict__ out) {
    int t = blockIdx.x * blockDim.x + threadIdx.x;
    int n = t >> 3;
    if (n >= NN) return;
    int sub = t & 7;

    int start = __ldg(g_rowoff + n);
    int d     = __ldg(g_deg + n);
    int end   = start + d;

    const uint4* __restrict__ src_buf = (STEP == 2) ? g_bufA : g_bufB;

    float a[8];
    #pragma unroll
    for (int q = 0; q < 8; q++) a[q] = 0.f;

    int j = start;
    #pragma unroll 2
    for (; j + 2 <= end; j += 2) {
        float2 e0 = __ldg(g_csr + j);
        float2 e1 = __ldg(g_csr + j + 1);
        uint4 r0 = __ldg(src_buf + __float_as_int(e0.x) * 8 + sub);
        uint4 r1 = __ldg(src_buf + __float_as_int(e1.x) * 8 + sub);
        acc8(a, r0, e0.y);
        acc8(a, r1, e1.y);
    }
    if (j < end) {
        float2 e0 = __ldg(g_csr + j);
        uint4 r0 = __ldg(src_buf + __float_as_int(e0.x) * 8 + sub);
        acc8(a, r0, e0.y);
    }

    if (STEP == 2) {
        __half2 h0 = __floats2half2_rn(a[0], a[1]);
        __half2 h1 = __floats2half2_rn(a[2], a[3]);
        __half2 h2 = __floats2half2_rn(a[4], a[5]);
        __half2 h3 = __floats2half2_rn(a[6], a[7]);
        uint4 w;
        w.x = *reinterpret_cast<unsigned*>(&h0);
        w.y = *reinterpret_cast<unsigned*>(&h1);
        w.z = *reinterpret_cast<unsigned*>(&h2);
        w.w = *reinterpret_cast<unsigned*>(&h3);
        g_bufB[n * 8 + sub] = w;
    } else {
        // Epilogue: read x1 (bufA), x2 (bufB), x0 (fp32 inputs); write out once.
        int hv = n * 8 + sub;              // uint4 index into half buffers
        float x1[8], x2[8];
        {
            uint4 ra = __ldg(g_bufA + hv);
            uint4 rb = __ldg(g_bufB + hv);
            __half2 h; float2 f;
            *reinterpret_cast<unsigned*>(&h) = ra.x; f = __half22float2(h); x1[0]=f.x; x1[1]=f.y;
            *reinterpret_cast<unsigned*>(&h) = ra.y; f = __half22float2(h); x1[2]=f.x; x1[3]=f.y;
            *reinterpret_cast<unsigned*>(&h) = ra.z; f = __half22float2(h); x1[4]=f.x; x1[5]=f.y;
            *reinterpret_cast<unsigned*>(&h) = ra.w; f = __half22float2(h); x1[6]=f.x; x1[7]=f.y;
            *reinterpret_cast<unsigned*>(&h) = rb.x; f = __half22float2(h); x2[0]=f.x; x2[1]=f.y;
            *reinterpret_cast<unsigned*>(&h) = rb.y; f = __half22float2(h); x2[2]=f.x; x2[3]=f.y;
            *reinterpret_cast<unsigned*>(&h) = rb.z; f = __half22float2(h); x2[4]=f.x; x2[5]=f.y;
            *reinterpret_cast<unsigned*>(&h) = rb.w; f = __half22float2(h); x2[6]=f.x; x2[7]=f.y;
        }
        int i0 = n * 16 + sub * 2;         // float4 index (this lane owns 2)
        bool isU = (n < NUM_USERS);
        const float4* base = isU ? uw : iw;
        int bi = isU ? i0 : (i0 - NUM_USERS * 16);
        float4 p0 = __ldg(base + bi);
        float4 p1 = __ldg(base + bi + 1);
        float4 o0, o1;
        o0.x = (p0.x + x1[0] + x2[0] + a[0]) * 0.25f;
        o0.y = (p0.y + x1[1] + x2[1] + a[1]) * 0.25f;
        o0.z = (p0.z + x1[2] + x2[2] + a[2]) * 0.25f;
        o0.w = (p0.w + x1[3] + x2[3] + a[3]) * 0.25f;
        o1.x = (p1.x + x1[4] + x2[4] + a[4]) * 0.25f;
        o1.y = (p1.y + x1[5] + x2[5] + a[5]) * 0.25f;
        o1.z = (p1.z + x1[6] + x2[6] + a[6]) * 0.25f;
        o1.w = (p1.w + x1[7] + x2[7] + a[7]) * 0.25f;
        __stcs(out + i0, o0);
        __stcs(out + i0 + 1, o1);
    }
}

extern "C" void kernel_launch(void* const* d_in, const int* in_sizes, int n_in,
                              void* d_out, int out_size) {
    const float4* uw  = (const float4*)d_in[0];
    const float4* iw  = (const float4*)d_in[1];
    const int*    ei  = (const int*)d_in[2];
    float4*       out = (float4*)d_out;

    const int B = 256;
    const int G_NE = (NE + B - 1) / B;
    const int G_P1 = (NN * 16 + B - 1) / B;
    const int G_P2 = (NN * 8 + B - 1) / B;

    k_pre<<<NB, B>>>(ei);
    k_count<<<G_NE, B>>>(ei);
    k_scan1<<<NB, B>>>();
    k_scan2<<<NB, B>>>();
    k_fill<<<G_NE, B>>>(ei);

    k_pull1<<<G_P1, B>>>(uw, iw);
    k_pull_h<2><<<G_P2, B>>>(uw, iw, out);
    k_pull_h<3><<<G_P2, B>>>(uw, iw, out);
}

// round 12
// speedup vs baseline: 4.9614x; 1.0703x over previous
#include <cuda_runtime.h>
#include <cuda_fp16.h>

// LightGCN: K=3 propagation, symmetric GCN norm, pull-based CSR (no float atomics).
// out = (x0 + x1 + x2 + x3) / 4,  x_{k+1}[d] = sum_{(s->d)} norm(e) * x_k[s].
// x0 converted once to fp16 (g_x0h); x1 -> bufA (fp16); x2 -> bufB (fp16);
// x3 stays in fp32 registers. All accumulation fp32; epilogue reads x0 in fp32.

constexpr int NUM_USERS = 100000;
constexpr int NUM_ITEMS = 50000;
constexpr int EMB       = 64;
constexpr int NE        = 1250000;
constexpr int NN        = NUM_USERS + NUM_ITEMS;
constexpr int NB        = (NN + 255) / 256;       // 586 scan blocks
constexpr int NH4       = NN * 8;                 // uint4 count of a half buffer

// Allocation-free scratch. One node row = 64 halves = 128 B = 8 uint4.
__device__ uint4  g_x0h[NH4];    // x0 (fp16)
__device__ uint4  g_bufA[NH4];   // x1 (fp16)
__device__ uint4  g_bufB[NH4];   // x2 (fp16)
__device__ int    g_deg[NN];
__device__ float  g_dis[NN];
__device__ int    g_rowoff[NN];
__device__ int    g_cursor[NN];
__device__ float2 g_csr[NE];     // {src (bitcast int), norm}
__device__ int    g_excl[NN];
__device__ int    g_bsum[NB];
__device__ int    g_is64;

// Zero degrees; detect int64-vs-int32 edge storage; convert x0 -> fp16 concat.
__global__ void k_pre(const int* __restrict__ raw,
                      const float4* __restrict__ uw,
                      const float4* __restrict__ iw) {
    int i = blockIdx.x * blockDim.x + threadIdx.x;
    if (i < NN) g_deg[i] = 0;
    if (i == 0) {
        int is64 = 1;
        #pragma unroll 1
        for (int k = 1; k < 128; k += 2)
            if (raw[k] != 0) { is64 = 0; break; }
        g_is64 = is64;
    }
    // fp16 conversion of x0: each thread handles one uint4 (8 halves = 2 float4).
    for (int v = i; v < NH4; v += gridDim.x * blockDim.x) {
        int f4 = v * 2;                    // first float4 index in concat space
        const float4* base = (f4 < NUM_USERS * 16) ? uw : iw;
        int bi = (f4 < NUM_USERS * 16) ? f4 : (f4 - NUM_USERS * 16);
        float4 p0 = __ldg(base + bi);
        float4 p1 = __ldg(base + bi + 1);
        __half2 h0 = __floats2half2_rn(p0.x, p0.y);
        __half2 h1 = __floats2half2_rn(p0.z, p0.w);
        __half2 h2 = __floats2half2_rn(p1.x, p1.y);
        __half2 h3 = __floats2half2_rn(p1.z, p1.w);
        uint4 w;
        w.x = *reinterpret_cast<unsigned*>(&h0);
        w.y = *reinterpret_cast<unsigned*>(&h1);
        w.z = *reinterpret_cast<unsigned*>(&h2);
        w.w = *reinterpret_cast<unsigned*>(&h3);
        g_x0h[v] = w;
    }
}

__global__ void k_count(const int* __restrict__ raw) {
    int e = blockIdx.x * blockDim.x + threadIdx.x;
    if (e >= NE) return;
    int dst = g_is64 ? raw[2 * ((size_t)NE + e)] : raw[NE + e];
    atomicAdd(&g_deg[dst], 1);
}

// Block-local exclusive scan of deg; also dis = deg^{-1/2} (0 for isolated).
__global__ void k_scan1() {
    __shared__ int s[256];
    int t = threadIdx.x;
    int i = blockIdx.x * 256 + t;
    int v = 0;
    if (i < NN) {
        v = g_deg[i];
        g_dis[i] = (v > 0) ? rsqrtf((float)v) : 0.0f;
    }
    s[t] = v;
    __syncthreads();
    #pragma unroll
    for (int o = 1; o < 256; o <<= 1) {
        int x = (t >= o) ? s[t - o] : 0;
        __syncthreads();
        s[t] += x;
        __syncthreads();
    }
    if (i < NN) g_excl[i] = s[t] - v;
    if (t == 255) g_bsum[blockIdx.x] = s[255];
}

// Each block reduces its own prefix over g_bsum, emits rowoff/cursor.
__global__ void k_scan2() {
    __shared__ int sm[256];
    int b = blockIdx.x;
    int t = threadIdx.x;
    int partial = 0;
    for (int k = t; k < b; k += 256) partial += g_bsum[k];
    sm[t] = partial;
    __syncthreads();
    #pragma unroll
    for (int o = 128; o > 0; o >>= 1) {
        if (t < o) sm[t] += sm[t + o];
        __syncthreads();
    }
    int pre = sm[0];
    int i = b * 256 + t;
    if (i < NN) {
        int off = g_excl[i] + pre;
        g_rowoff[i] = off;
        g_cursor[i] = off;
    }
}

// Fill CSR: slot per edge via atomic cursor; pack {src, norm} into one float2.
__global__ void k_fill(const int* __restrict__ raw) {
    int e = blockIdx.x * blockDim.x + threadIdx.x;
    if (e >= NE) return;
    int src, dst;
    if (g_is64) {
        src = raw[2 * (size_t)e];
        dst = raw[2 * ((size_t)NE + e)];
    } else {
        src = raw[e];
        dst = raw[NE + e];
    }
    float norm = __ldg(g_dis + src) * __ldg(g_dis + dst);
    int pos = atomicAdd(&g_cursor[dst], 1);
    g_csr[pos] = make_float2(__int_as_float(src), norm);
}

// Pull steps: 8 lanes/row, each lane owns 8 halves (one uint4 = 16B).
// Gather fp16, accumulate fp32.
// STEP1: x0h -> bufA.  STEP2: bufA -> bufB.
// STEP3: bufB -> out = (x0_fp32 + x1 + x2 + acc) * 0.25, streaming store.
__device__ __forceinline__ void acc8(float* a, uint4 r, float nm) {
    __half2 h;
    float2 f;
    *reinterpret_cast<unsigned*>(&h) = r.x; f = __half22float2(h);
    a[0] += f.x * nm; a[1] += f.y * nm;
    *reinterpret_cast<unsigned*>(&h) = r.y; f = __half22float2(h);
    a[2] += f.x * nm; a[3] += f.y * nm;
    *reinterpret_cast<unsigned*>(&h) = r.z; f = __half22float2(h);
    a[4] += f.x * nm; a[5] += f.y * nm;
    *reinterpret_cast<unsigned*>(&h) = r.w; f = __half22float2(h);
    a[6] += f.x * nm; a[7] += f.y * nm;
}

__device__ __forceinline__ uint4 pack8(const float* a) {
    __half2 h0 = __floats2half2_rn(a[0], a[1]);
    __half2 h1 = __floats2half2_rn(a[2], a[3]);
    __half2 h2 = __floats2half2_rn(a[4], a[5]);
    __half2 h3 = __floats2half2_rn(a[6], a[7]);
    uint4 w;
    w.x = *reinterpret_cast<unsigned*>(&h0);
    w.y = *reinterpret_cast<unsigned*>(&h1);
    w.z = *reinterpret_cast<unsigned*>(&h2);
    w.w = *reinterpret_cast<unsigned*>(&h3);
    return w;
}

template <int STEP>
__global__ void __launch_bounds__(256) k_pull(const float4* __restrict__ uw,
                                              const float4* __restrict__ iw,
                                              float4* __restrict__ out) {
    int t = blockIdx.x * blockDim.x + threadIdx.x;
    int n = t >> 3;
    if (n >= NN) return;
    int sub = t & 7;

    int start = __ldg(g_rowoff + n);
    int d     = __ldg(g_deg + n);
    int end   = start + d;

    const uint4* __restrict__ src_buf =
        (STEP == 1) ? g_x0h : (STEP == 2) ? g_bufA : g_bufB;

    float a[8];
    #pragma unroll
    for (int q = 0; q < 8; q++) a[q] = 0.f;

    int j = start;
    #pragma unroll 2
    for (; j + 2 <= end; j += 2) {
        float2 e0 = __ldg(g_csr + j);
        float2 e1 = __ldg(g_csr + j + 1);
        uint4 r0 = __ldg(src_buf + __float_as_int(e0.x) * 8 + sub);
        uint4 r1 = __ldg(src_buf + __float_as_int(e1.x) * 8 + sub);
        acc8(a, r0, e0.y);
        acc8(a, r1, e1.y);
    }
    if (j < end) {
        float2 e0 = __ldg(g_csr + j);
        uint4 r0 = __ldg(src_buf + __float_as_int(e0.x) * 8 + sub);
        acc8(a, r0, e0.y);
    }

    int hv = n * 8 + sub;
    if (STEP == 1) {
        g_bufA[hv] = pack8(a);
    } else if (STEP == 2) {
        g_bufB[hv] = pack8(a);
    } else {
        // Epilogue: x1 (bufA), x2 (bufB) in fp16; x0 in fp32; write out once.
        float x1[8], x2[8];
        {
            uint4 ra = __ldg(g_bufA + hv);
            uint4 rb = __ldg(g_bufB + hv);
            __half2 h; float2 f;
            *reinterpret_cast<unsigned*>(&h) = ra.x; f = __half22float2(h); x1[0]=f.x; x1[1]=f.y;
            *reinterpret_cast<unsigned*>(&h) = ra.y; f = __half22float2(h); x1[2]=f.x; x1[3]=f.y;
            *reinterpret_cast<unsigned*>(&h) = ra.z; f = __half22float2(h); x1[4]=f.x; x1[5]=f.y;
            *reinterpret_cast<unsigned*>(&h) = ra.w; f = __half22float2(h); x1[6]=f.x; x1[7]=f.y;
            *reinterpret_cast<unsigned*>(&h) = rb.x; f = __half22float2(h); x2[0]=f.x; x2[1]=f.y;
            *reinterpret_cast<unsigned*>(&h) = rb.y; f = __half22float2(h); x2[2]=f.x; x2[3]=f.y;
            *reinterpret_cast<unsigned*>(&h) = rb.z; f = __half22float2(h); x2[4]=f.x; x2[5]=f.y;
            *reinterpret_cast<unsigned*>(&h) = rb.w; f = __half22float2(h); x2[6]=f.x; x2[7]=f.y;
        }
        int i0 = n * 16 + sub * 2;          // float4 index (this lane owns 2)
        bool isU = (n < NUM_USERS);
        const float4* base = isU ? uw : iw;
        int bi = isU ? i0 : (i0 - NUM_USERS * 16);
        float4 p0 = __ldg(base + bi);
        float4 p1 = __ldg(base + bi + 1);
        float4 o0, o1;
        o0.x = (p0.x + x1[0] + x2[0] + a[0]) * 0.25f;
        o0.y = (p0.y + x1[1] + x2[1] + a[1]) * 0.25f;
        o0.z = (p0.z + x1[2] + x2[2] + a[2]) * 0.25f;
        o0.w = (p0.w + x1[3] + x2[3] + a[3]) * 0.25f;
        o1.x = (p1.x + x1[4] + x2[4] + a[4]) * 0.25f;
        o1.y = (p1.y + x1[5] + x2[5] + a[5]) * 0.25f;
        o1.z = (p1.z + x1[6] + x2[6] + a[6]) * 0.25f;
        o1.w = (p1.w + x1[7] + x2[7] + a[7]) * 0.25f;
        __stcs(out + i0, o0);
        __stcs(out + i0 + 1, o1);
    }
}

extern "C" void kernel_launch(void* const* d_in, const int* in_sizes, int n_in,
                              void* d_out, int out_size) {
    const float4* uw  = (const float4*)d_in[0];
    const float4* iw  = (const float4*)d_in[1];
    const int*    ei  = (const int*)d_in[2];
    float4*       out = (float4*)d_out;

    const int B = 256;
    const int G_NE  = (NE + B - 1) / B;
    const int G_P   = (NN * 8 + B - 1) / B;
    const int G_PRE = (NH4 + B - 1) / B;    // covers conversion + deg zero

    k_pre<<<G_PRE, B>>>(ei, uw, iw);
    k_count<<<G_NE, B>>>(ei);
    k_scan1<<<NB, B>>>();
    k_scan2<<<NB, B>>>();
    k_fill<<<G_NE, B>>>(ei);

    k_pull<1><<<G_P, B>>>(uw, iw, out);
    k_pull<2><<<G_P, B>>>(uw, iw, out);
    k_pull<3><<<G_P, B>>>(uw, iw, out);
}

// round 14
// speedup vs baseline: 5.1377x; 1.0355x over previous
#include <cuda_runtime.h>
#include <cuda_fp16.h>

// LightGCN: K=3 propagation, symmetric GCN norm, pull-based CSR (no float atomics).
// out = (x0 + x1 + x2 + x3) / 4,  x_{k+1}[d] = sum_{(s->d)} norm(e) * x_k[s].
// x0 converted once to fp16 (g_x0h); x1 -> bufA (fp16); x2 -> bufB (fp16);
// x3 stays in fp32 registers. All accumulation fp32; fp16 only at rest.

constexpr int NUM_USERS = 100000;
constexpr int NUM_ITEMS = 50000;
constexpr int EMB       = 64;
constexpr int NE        = 1250000;
constexpr int NN        = NUM_USERS + NUM_ITEMS;
constexpr int NB        = (NN + 255) / 256;       // 586 scan blocks
constexpr int NH4       = NN * 8;                 // uint4 count of a half buffer

// Allocation-free scratch. One node row = 64 halves = 128 B = 8 uint4.
__device__ uint4  g_x0h[NH4];    // x0 (fp16)
__device__ uint4  g_bufA[NH4];   // x1 (fp16)
__device__ uint4  g_bufB[NH4];   // x2 (fp16)
__device__ int    g_deg[NN];
__device__ float  g_dis[NN];
__device__ int    g_rowoff[NN];
__device__ int    g_cursor[NN];
__device__ float2 g_csr[NE];     // {src (bitcast int), norm}
__device__ int    g_excl[NN];
__device__ int    g_bsum[NB];
__device__ int    g_is64;

// Zero degrees; detect int64-vs-int32 edge storage; convert x0 -> fp16 concat.
__global__ void k_pre(const int* __restrict__ raw,
                      const float4* __restrict__ uw,
                      const float4* __restrict__ iw) {
    int i = blockIdx.x * blockDim.x + threadIdx.x;
    if (i < NN) g_deg[i] = 0;
    if (i == 0) {
        int is64 = 1;
        #pragma unroll 1
        for (int k = 1; k < 128; k += 2)
            if (raw[k] != 0) { is64 = 0; break; }
        g_is64 = is64;
    }
    for (int v = i; v < NH4; v += gridDim.x * blockDim.x) {
        int f4 = v * 2;
        const float4* base = (f4 < NUM_USERS * 16) ? uw : iw;
        int bi = (f4 < NUM_USERS * 16) ? f4 : (f4 - NUM_USERS * 16);
        float4 p0 = __ldg(base + bi);
        float4 p1 = __ldg(base + bi + 1);
        __half2 h0 = __floats2half2_rn(p0.x, p0.y);
        __half2 h1 = __floats2half2_rn(p0.z, p0.w);
        __half2 h2 = __floats2half2_rn(p1.x, p1.y);
        __half2 h3 = __floats2half2_rn(p1.z, p1.w);
        uint4 w;
        w.x = *reinterpret_cast<unsigned*>(&h0);
        w.y = *reinterpret_cast<unsigned*>(&h1);
        w.z = *reinterpret_cast<unsigned*>(&h2);
        w.w = *reinterpret_cast<unsigned*>(&h3);
        g_x0h[v] = w;
    }
}

__global__ void k_count(const int* __restrict__ raw) {
    int e = blockIdx.x * blockDim.x + threadIdx.x;
    if (e >= NE) return;
    int dst = g_is64 ? raw[2 * ((size_t)NE + e)] : raw[NE + e];
    atomicAdd(&g_deg[dst], 1);
}

// Block-local exclusive scan of deg via warp shuffles (2 barriers total);
// also dis = deg^{-1/2} (0 for isolated).
__global__ void k_scan1() {
    __shared__ int wsum[8];
    int t = threadIdx.x;
    int lane = t & 31, w = t >> 5;
    int i = blockIdx.x * 256 + t;
    int v = 0;
    if (i < NN) {
        v = g_deg[i];
        g_dis[i] = (v > 0) ? rsqrtf((float)v) : 0.0f;
    }
    // warp-inclusive scan
    int s = v;
    #pragma unroll
    for (int o = 1; o < 32; o <<= 1) {
        int x = __shfl_up_sync(0xffffffffu, s, o);
        if (lane >= o) s += x;
    }
    if (lane == 31) wsum[w] = s;
    __syncthreads();
    // warp 0 scans the 8 warp totals
    if (w == 0) {
        int ws = (lane < 8) ? wsum[lane] : 0;
        #pragma unroll
        for (int o = 1; o < 8; o <<= 1) {
            int x = __shfl_up_sync(0xffffffffu, ws, o);
            if (lane >= o) ws += x;
        }
        if (lane < 8) wsum[lane] = ws;
    }
    __syncthreads();
    int base = (w > 0) ? wsum[w - 1] : 0;
    if (i < NN) g_excl[i] = base + s - v;        // exclusive
    if (t == 255) g_bsum[blockIdx.x] = base + s; // block total
}

// Each block computes its prefix over g_bsum with a shuffle reduce, emits rowoff/cursor.
__global__ void k_scan2() {
    __shared__ int wsum[8];
    int b = blockIdx.x;
    int t = threadIdx.x;
    int lane = t & 31, w = t >> 5;
    int partial = 0;
    for (int k = t; k < b; k += 256) partial += g_bsum[k];
    #pragma unroll
    for (int o = 16; o > 0; o >>= 1)
        partial += __shfl_down_sync(0xffffffffu, partial, o);
    if (lane == 0) wsum[w] = partial;
    __syncthreads();
    int pre;
    {
        int x = (t < 8) ? wsum[t] : 0;  // all threads compute same sum via warp 0 broadcast
        if (w == 0) {
            #pragma unroll
            for (int o = 4; o > 0; o >>= 1)
                x += __shfl_down_sync(0xffu, x, o);
            if (lane == 0) wsum[0] = x;
        }
        __syncthreads();
        pre = wsum[0];
    }
    int i = b * 256 + t;
    if (i < NN) {
        int off = g_excl[i] + pre;
        g_rowoff[i] = off;
        g_cursor[i] = off;
    }
}

// Fill CSR: slot per edge via atomic cursor; pack {src, norm} into one float2.
__global__ void k_fill(const int* __restrict__ raw) {
    int e = blockIdx.x * blockDim.x + threadIdx.x;
    if (e >= NE) return;
    int src, dst;
    if (g_is64) {
        src = raw[2 * (size_t)e];
        dst = raw[2 * ((size_t)NE + e)];
    } else {
        src = raw[e];
        dst = raw[NE + e];
    }
    float norm = __ldg(g_dis + src) * __ldg(g_dis + dst);
    int pos = atomicAdd(&g_cursor[dst], 1);
    g_csr[pos] = make_float2(__int_as_float(src), norm);
}

// Pull steps: 8 lanes/row, each lane owns 8 halves (one uint4 = 16B).
// Gather fp16, accumulate fp32. Inner loop: 4 edges/iter, 4 gathers in flight.
// STEP1: x0h -> bufA.  STEP2: bufA -> bufB.
// STEP3: bufB -> out = (x0 + x1 + x2 + acc) * 0.25, streaming store.
__device__ __forceinline__ void acc8(float* a, uint4 r, float nm) {
    __half2 h;
    float2 f;
    *reinterpret_cast<unsigned*>(&h) = r.x; f = __half22float2(h);
    a[0] += f.x * nm; a[1] += f.y * nm;
    *reinterpret_cast<unsigned*>(&h) = r.y; f = __half22float2(h);
    a[2] += f.x * nm; a[3] += f.y * nm;
    *reinterpret_cast<unsigned*>(&h) = r.z; f = __half22float2(h);
    a[4] += f.x * nm; a[5] += f.y * nm;
    *reinterpret_cast<unsigned*>(&h) = r.w; f = __half22float2(h);
    a[6] += f.x * nm; a[7] += f.y * nm;
}

__device__ __forceinline__ void unpack8(uint4 r, float* x) {
    __half2 h; float2 f;
    *reinterpret_cast<unsigned*>(&h) = r.x; f = __half22float2(h); x[0] = f.x; x[1] = f.y;
    *reinterpret_cast<unsigned*>(&h) = r.y; f = __half22float2(h); x[2] = f.x; x[3] = f.y;
    *reinterpret_cast<unsigned*>(&h) = r.z; f = __half22float2(h); x[4] = f.x; x[5] = f.y;
    *reinterpret_cast<unsigned*>(&h) = r.w; f = __half22float2(h); x[6] = f.x; x[7] = f.y;
}

__device__ __forceinline__ uint4 pack8(const float* a) {
    __half2 h0 = __floats2half2_rn(a[0], a[1]);
    __half2 h1 = __floats2half2_rn(a[2], a[3]);
    __half2 h2 = __floats2half2_rn(a[4], a[5]);
    __half2 h3 = __floats2half2_rn(a[6], a[7]);
    uint4 w;
    w.x = *reinterpret_cast<unsigned*>(&h0);
    w.y = *reinterpret_cast<unsigned*>(&h1);
    w.z = *reinterpret_cast<unsigned*>(&h2);
    w.w = *reinterpret_cast<unsigned*>(&h3);
    return w;
}

template <int STEP>
__global__ void __launch_bounds__(256) k_pull(float4* __restrict__ out) {
    int t = blockIdx.x * blockDim.x + threadIdx.x;
    int n = t >> 3;
    if (n >= NN) return;
    int sub = t & 7;

    int start = __ldg(g_rowoff + n);
    int d     = __ldg(g_deg + n);
    int end   = start + d;

    const uint4* __restrict__ src_buf =
        (STEP == 1) ? g_x0h : (STEP == 2) ? g_bufA : g_bufB;

    float a[8];
    #pragma unroll
    for (int q = 0; q < 8; q++) a[q] = 0.f;

    int j = start;
    for (; j + 4 <= end; j += 4) {
        float2 e0 = __ldg(g_csr + j);
        float2 e1 = __ldg(g_csr + j + 1);
        float2 e2 = __ldg(g_csr + j + 2);
        float2 e3 = __ldg(g_csr + j + 3);
        uint4 r0 = __ldg(src_buf + __float_as_int(e0.x) * 8 + sub);
        uint4 r1 = __ldg(src_buf + __float_as_int(e1.x) * 8 + sub);
        uint4 r2 = __ldg(src_buf + __float_as_int(e2.x) * 8 + sub);
        uint4 r3 = __ldg(src_buf + __float_as_int(e3.x) * 8 + sub);
        acc8(a, r0, e0.y);
        acc8(a, r1, e1.y);
        acc8(a, r2, e2.y);
        acc8(a, r3, e3.y);
    }
    for (; j < end; j++) {
        float2 e0 = __ldg(g_csr + j);
        uint4 r0 = __ldg(src_buf + __float_as_int(e0.x) * 8 + sub);
        acc8(a, r0, e0.y);
    }

    int hv = n * 8 + sub;
    if (STEP == 1) {
        g_bufA[hv] = pack8(a);
    } else if (STEP == 2) {
        g_bufB[hv] = pack8(a);
    } else {
        // Epilogue: x0 (x0h), x1 (bufA), x2 (bufB) all fp16; write out once (fp32).
        float x0[8], x1[8], x2[8];
        unpack8(__ldg(g_x0h + hv), x0);
        unpack8(__ldg(g_bufA + hv), x1);
        unpack8(__ldg(g_bufB + hv), x2);
        int i0 = n * 16 + sub * 2;          // float4 index (this lane owns 2)
        float4 o0, o1;
        o0.x = (x0[0] + x1[0] + x2[0] + a[0]) * 0.25f;
        o0.y = (x0[1] + x1[1] + x2[1] + a[1]) * 0.25f;
        o0.z = (x0[2] + x1[2] + x2[2] + a[2]) * 0.25f;
        o0.w = (x0[3] + x1[3] + x2[3] + a[3]) * 0.25f;
        o1.x = (x0[4] + x1[4] + x2[4] + a[4]) * 0.25f;
        o1.y = (x0[5] + x1[5] + x2[5] + a[5]) * 0.25f;
        o1.z = (x0[6] + x1[6] + x2[6] + a[6]) * 0.25f;
        o1.w = (x0[7] + x1[7] + x2[7] + a[7]) * 0.25f;
        __stcs(out + i0, o0);
        __stcs(out + i0 + 1, o1);
    }
}

extern "C" void kernel_launch(void* const* d_in, const int* in_sizes, int n_in,
                              void* d_out, int out_size) {
    const float4* uw  = (const float4*)d_in[0];
    const float4* iw  = (const float4*)d_in[1];
    const int*    ei  = (const int*)d_in[2];
    float4*       out = (float4*)d_out;

    const int B = 256;
    const int G_NE  = (NE + B - 1) / B;
    const int G_P   = (NN * 8 + B - 1) / B;
    const int G_PRE = (NH4 + B - 1) / B;

    k_pre<<<G_PRE, B>>>(ei, uw, iw);
    k_count<<<G_NE, B>>>(ei);
    k_scan1<<<NB, B>>>();
    k_scan2<<<NB, B>>>();
    k_fill<<<G_NE, B>>>(ei);

    k_pull<1><<<G_P, B>>>(out);
    k_pull<2><<<G_P, B>>>(out);
    k_pull<3><<<G_P, B>>>(out);
}

// round 17
// speedup vs baseline: 5.6405x; 1.0979x over previous
#include <cuda_runtime.h>
#include <cuda_fp16.h>

// LightGCN: K=3 propagation, symmetric GCN norm, pull-based CSR (no float atomics).
// out = (x0 + x1 + x2 + x3) / 4,  x_{k+1}[d] = sum_{(s->d)} norm(e) * x_k[s].
// x0 -> g_x0h (fp16, once); x1 -> bufA (fp16); x2 -> bufB (fp16); x3 in fp32 regs.
// 6 launches: prep(convert+detect+count), scan(single-pass), fill, pull x3.
// Self-cleaning: pull3 re-zeros g_deg / g_base for the next replay.

constexpr int NUM_USERS = 100000;
constexpr int NUM_ITEMS = 50000;
constexpr int EMB       = 64;
constexpr int NE        = 1250000;
constexpr int NN        = NUM_USERS + NUM_ITEMS;
constexpr int NB        = (NN + 255) / 256;       // 586 scan blocks
constexpr int NH4       = NN * 8;                 // uint4 count of a half buffer

// Allocation-free scratch. One node row = 64 halves = 128 B = 8 uint4.
__device__ uint4  g_x0h[NH4];    // x0 (fp16)
__device__ uint4  g_bufA[NH4];   // x1 (fp16)
__device__ uint4  g_bufB[NH4];   // x2 (fp16)
__device__ int    g_deg[NN];     // zeroed by previous replay's pull3 (BSS-zero run 1)
__device__ float  g_dis[NN];
__device__ int2   g_range[NN];   // CSR {start, end} per node
__device__ int    g_cursor[NN];
__device__ float2 g_csr[NE];     // {src (bitcast int), norm}
__device__ int    g_base;        // scan grid base (reset by pull3)
__device__ int    g_is64;

// Convert x0 -> fp16 concat; count in-degrees. Layout detection per block
// (indices < 150000 => int64 little-endian has zero high words at odd positions).
__global__ void k_prep(const int* __restrict__ raw,
                       const float4* __restrict__ uw,
                       const float4* __restrict__ iw) {
    __shared__ int s_is64;
    if (threadIdx.x == 0) {
        int is64 = 1;
        #pragma unroll 1
        for (int k = 1; k < 128; k += 2)
            if (raw[k] != 0) { is64 = 0; break; }
        s_is64 = is64;
        if (blockIdx.x == 0) g_is64 = is64;   // consumed by k_fill
    }
    __syncthreads();
    int is64 = s_is64;

    int i = blockIdx.x * blockDim.x + threadIdx.x;
    int stride = gridDim.x * blockDim.x;

    // fp16 conversion of x0: one uint4 (8 halves = 2 float4) per index.
    for (int v = i; v < NH4; v += stride) {
        int f4 = v * 2;
        const float4* base = (f4 < NUM_USERS * 16) ? uw : iw;
        int bi = (f4 < NUM_USERS * 16) ? f4 : (f4 - NUM_USERS * 16);
        float4 p0 = __ldg(base + bi);
        float4 p1 = __ldg(base + bi + 1);
        __half2 h0 = __floats2half2_rn(p0.x, p0.y);
        __half2 h1 = __floats2half2_rn(p0.z, p0.w);
        __half2 h2 = __floats2half2_rn(p1.x, p1.y);
        __half2 h3 = __floats2half2_rn(p1.z, p1.w);
        uint4 w;
        w.x = *reinterpret_cast<unsigned*>(&h0);
        w.y = *reinterpret_cast<unsigned*>(&h1);
        w.z = *reinterpret_cast<unsigned*>(&h2);
        w.w = *reinterpret_cast<unsigned*>(&h3);
        g_x0h[v] = w;
    }

    // In-degree count (g_deg pre-zeroed by previous replay / BSS).
    for (int e = i; e < NE; e += stride) {
        int dst = is64 ? raw[2 * ((size_t)NE + e)] : raw[NE + e];
        atomicAdd(&g_deg[dst], 1);
    }
}

// Single-pass scan: block-local shuffle scan + atomic grid base.
// Emits g_range {start,end}, g_cursor, g_dis. Base ordering is nondeterministic,
// which only permutes CSR row placement (sum order already atomic-nondeterministic).
__global__ void k_scan() {
    __shared__ int wsum[8];
    __shared__ int s_base;
    int t = threadIdx.x;
    int lane = t & 31, w = t >> 5;
    int i = blockIdx.x * 256 + t;

    int v = 0;
    if (i < NN) {
        v = g_deg[i];
        g_dis[i] = (v > 0) ? rsqrtf((float)v) : 0.0f;
    }
    // warp-inclusive scan
    int s = v;
    #pragma unroll
    for (int o = 1; o < 32; o <<= 1) {
        int x = __shfl_up_sync(0xffffffffu, s, o);
        if (lane >= o) s += x;
    }
    if (lane == 31) wsum[w] = s;
    __syncthreads();
    if (w == 0) {
        int ws = (lane < 8) ? wsum[lane] : 0;
        #pragma unroll
        for (int o = 1; o < 8; o <<= 1) {
            int x = __shfl_up_sync(0xffffffffu, ws, o);
            if (lane >= o) ws += x;
        }
        if (lane < 8) wsum[lane] = ws;
    }
    __syncthreads();
    int wbase = (w > 0) ? wsum[w - 1] : 0;
    int btotal = wsum[7];
    if (t == 0) s_base = atomicAdd(&g_base, btotal);
    __syncthreads();
    if (i < NN) {
        int off = s_base + wbase + s - v;   // exclusive
        g_range[i]  = make_int2(off, off + v);
        g_cursor[i] = off;
    }
}

// Fill CSR: slot per edge via atomic cursor; pack {src, norm} into one float2.
__global__ void k_fill(const int* __restrict__ raw) {
    int e = blockIdx.x * blockDim.x + threadIdx.x;
    if (e >= NE) return;
    int src, dst;
    if (g_is64) {
        src = raw[2 * (size_t)e];
        dst = raw[2 * ((size_t)NE + e)];
    } else {
        src = raw[e];
        dst = raw[NE + e];
    }
    float norm = __ldg(g_dis + src) * __ldg(g_dis + dst);
    int pos = atomicAdd(&g_cursor[dst], 1);
    g_csr[pos] = make_float2(__int_as_float(src), norm);
}

// Pull steps: 8 lanes/row, each lane owns 8 halves (one uint4 = 16B).
// Gather fp16, accumulate fp32. Inner loop: 4 edges/iter, 4 gathers in flight.
// STEP1: x0h -> bufA.  STEP2: bufA -> bufB.
// STEP3: bufB -> out = (x0 + x1 + x2 + acc) * 0.25 (streaming), then self-clean.
__device__ __forceinline__ void acc8(float* a, uint4 r, float nm) {
    __half2 h;
    float2 f;
    *reinterpret_cast<unsigned*>(&h) = r.x; f = __half22float2(h);
    a[0] += f.x * nm; a[1] += f.y * nm;
    *reinterpret_cast<unsigned*>(&h) = r.y; f = __half22float2(h);
    a[2] += f.x * nm; a[3] += f.y * nm;
    *reinterpret_cast<unsigned*>(&h) = r.z; f = __half22float2(h);
    a[4] += f.x * nm; a[5] += f.y * nm;
    *reinterpret_cast<unsigned*>(&h) = r.w; f = __half22float2(h);
    a[6] += f.x * nm; a[7] += f.y * nm;
}

__device__ __forceinline__ void unpack8(uint4 r, float* x) {
    __half2 h; float2 f;
    *reinterpret_cast<unsigned*>(&h) = r.x; f = __half22float2(h); x[0] = f.x; x[1] = f.y;
    *reinterpret_cast<unsigned*>(&h) = r.y; f = __half22float2(h); x[2] = f.x; x[3] = f.y;
    *reinterpret_cast<unsigned*>(&h) = r.z; f = __half22float2(h); x[4] = f.x; x[5] = f.y;
    *reinterpret_cast<unsigned*>(&h) = r.w; f = __half22float2(h); x[6] = f.x; x[7] = f.y;
}

__device__ __forceinline__ uint4 pack8(const float* a) {
    __half2 h0 = __floats2half2_rn(a[0], a[1]);
    __half2 h1 = __floats2half2_rn(a[2], a[3]);
    __half2 h2 = __floats2half2_rn(a[4], a[5]);
    __half2 h3 = __floats2half2_rn(a[6], a[7]);
    uint4 w;
    w.x = *reinterpret_cast<unsigned*>(&h0);
    w.y = *reinterpret_cast<unsigned*>(&h1);
    w.z = *reinterpret_cast<unsigned*>(&h2);
    w.w = *reinterpret_cast<unsigned*>(&h3);
    return w;
}

template <int STEP>
__global__ void __launch_bounds__(256) k_pull(float4* __restrict__ out) {
    int t = blockIdx.x * blockDim.x + threadIdx.x;
    int n = t >> 3;
    if (n >= NN) return;
    int sub = t & 7;

    int2 rng = __ldg(g_range + n);      // 8 lanes same addr -> broadcast
    int j = rng.x, end = rng.y;

    const uint4* __restrict__ src_buf =
        (STEP == 1) ? g_x0h : (STEP == 2) ? g_bufA : g_bufB;

    float a[8];
    #pragma unroll
    for (int q = 0; q < 8; q++) a[q] = 0.f;

    for (; j + 4 <= end; j += 4) {
        float2 e0 = __ldg(g_csr + j);
        float2 e1 = __ldg(g_csr + j + 1);
        float2 e2 = __ldg(g_csr + j + 2);
        float2 e3 = __ldg(g_csr + j + 3);
        uint4 r0 = __ldg(src_buf + __float_as_int(e0.x) * 8 + sub);
        uint4 r1 = __ldg(src_buf + __float_as_int(e1.x) * 8 + sub);
        uint4 r2 = __ldg(src_buf + __float_as_int(e2.x) * 8 + sub);
        uint4 r3 = __ldg(src_buf + __float_as_int(e3.x) * 8 + sub);
        acc8(a, r0, e0.y);
        acc8(a, r1, e1.y);
        acc8(a, r2, e2.y);
        acc8(a, r3, e3.y);
    }
    for (; j < end; j++) {
        float2 e0 = __ldg(g_csr + j);
        uint4 r0 = __ldg(src_buf + __float_as_int(e0.x) * 8 + sub);
        acc8(a, r0, e0.y);
    }

    int hv = n * 8 + sub;
    if (STEP == 1) {
        g_bufA[hv] = pack8(a);
    } else if (STEP == 2) {
        g_bufB[hv] = pack8(a);
    } else {
        // Epilogue: x0 (x0h), x1 (bufA), x2 (bufB) all fp16; write out once (fp32).
        float x0[8], x1[8], x2[8];
        unpack8(__ldg(g_x0h + hv), x0);
        unpack8(__ldg(g_bufA + hv), x1);
        unpack8(__ldg(g_bufB + hv), x2);
        int i0 = n * 16 + sub * 2;          // float4 index (this lane owns 2)
        float4 o0, o1;
        o0.x = (x0[0] + x1[0] + x2[0] + a[0]) * 0.25f;
        o0.y = (x0[1] + x1[1] + x2[1] + a[1]) * 0.25f;
        o0.z = (x0[2] + x1[2] + x2[2] + a[2]) * 0.25f;
        o0.w = (x0[3] + x1[3] + x2[3] + a[3]) * 0.25f;
        o1.x = (x0[4] + x1[4] + x2[4] + a[4]) * 0.25f;
        o1.y = (x0[5] + x1[5] + x2[5] + a[5]) * 0.25f;
        o1.z = (x0[6] + x1[6] + x2[6] + a[6]) * 0.25f;
        o1.w = (x0[7] + x1[7] + x2[7] + a[7]) * 0.25f;
        __stcs(out + i0, o0);
        __stcs(out + i0 + 1, o1);
        // Self-clean for the next replay (graph replays the same launches).
        if (sub == 0) g_deg[n] = 0;
        if (t == 0)   g_base = 0;
    }
}

extern "C" void kernel_launch(void* const* d_in, const int* in_sizes, int n_in,
                              void* d_out, int out_size) {
    const float4* uw  = (const float4*)d_in[0];
    const float4* iw  = (const float4*)d_in[1];
    const int*    ei  = (const int*)d_in[2];
    float4*       out = (float4*)d_out;

    const int B = 256;
    const int G_NE = (NE + B - 1) / B;
    const int G_P  = (NN * 8 + B - 1) / B;

    k_prep<<<G_NE, B>>>(ei, uw, iw);
    k_scan<<<NB, B>>>();
    k_fill<<<G_NE, B>>>(ei);

    k_pull<1><<<G_P, B>>>(out);
    k_pull<2><<<G_P, B>>>(out);
    k_pull<3><<<G_P, B>>>(out);
}